// round 6
// baseline (speedup 1.0000x reference)
#include <cuda_runtime.h>

// Pixel-wise diagonal RNN:
//   h_t = leaky_relu(W_ih * x_t + W_hh * h_{t-1} + b_hh), h_0 = 0
// Streaming-bound: ~443 MB read + 419 MB write. Strategy:
//  - 2x float4 per thread (32B granularity)
//  - t-loop unrolled by 2 with batched loads (4x LDG.128 in flight)
//    and batched stores (longer same-direction DRAM bursts)
//  - __ldcs / __stcs streaming hints (no reuse anywhere)
//  - h carried in registers across the T loop

#ifndef NEG_SLOPE
#define NEG_SLOPE 0.01f
#endif

__device__ __forceinline__ float4 rnn_step(float4 wi, float4 wh, float4 b,
                                           float4 xv, float4 h)
{
    float4 v;
    v.x = fmaf(wi.x, xv.x, fmaf(wh.x, h.x, b.x));
    v.y = fmaf(wi.y, xv.y, fmaf(wh.y, h.y, b.y));
    v.z = fmaf(wi.z, xv.z, fmaf(wh.z, h.z, b.z));
    v.w = fmaf(wi.w, xv.w, fmaf(wh.w, h.w, b.w));
    float4 r;
    r.x = fmaxf(v.x, NEG_SLOPE * v.x);
    r.y = fmaxf(v.y, NEG_SLOPE * v.y);
    r.z = fmaxf(v.z, NEG_SLOPE * v.z);
    r.w = fmaxf(v.w, NEG_SLOPE * v.w);
    return r;
}

__global__ __launch_bounds__(256) void pixelwise_rnn_kernel(
    const float4* __restrict__ x,     // (T, P/4)
    const float4* __restrict__ w_ih,  // (P/4)
    const float4* __restrict__ w_hh,  // (P/4)
    const float4* __restrict__ b_hh,  // (P/4)
    float4* __restrict__ out,         // (T, P/4)
    int P4, int T)
{
    // each thread owns two adjacent float4s: indices 2*tid, 2*tid+1
    int p = 2 * (blockIdx.x * blockDim.x + threadIdx.x);

    const float4 wi0 = w_ih[p],   wi1 = w_ih[p + 1];
    const float4 wh0 = w_hh[p],   wh1 = w_hh[p + 1];
    const float4 b0  = b_hh[p],   b1  = b_hh[p + 1];

    float4 h0 = make_float4(0.f, 0.f, 0.f, 0.f);
    float4 h1 = make_float4(0.f, 0.f, 0.f, 0.f);

    const float4* xp = x + p;
    float4* op = out + p;

    // T = 50: process two timesteps per iteration, batching the 4 loads
    // up front and the 4 stores at the end for longer DRAM bursts.
    #pragma unroll 5
    for (int t = 0; t < T; t += 2) {
        size_t offa = (size_t)t * P4;
        size_t offb = offa + P4;

        float4 xa0 = __ldcs(xp + offa);
        float4 xa1 = __ldcs(xp + offa + 1);
        float4 xb0 = __ldcs(xp + offb);
        float4 xb1 = __ldcs(xp + offb + 1);

        float4 ha0 = rnn_step(wi0, wh0, b0, xa0, h0);
        float4 ha1 = rnn_step(wi1, wh1, b1, xa1, h1);
        float4 hb0 = rnn_step(wi0, wh0, b0, xb0, ha0);
        float4 hb1 = rnn_step(wi1, wh1, b1, xb1, ha1);

        __stcs(op + offa,     ha0);
        __stcs(op + offa + 1, ha1);
        __stcs(op + offb,     hb0);
        __stcs(op + offb + 1, hb1);

        h0 = hb0;
        h1 = hb1;
    }
}

extern "C" void kernel_launch(void* const* d_in, const int* in_sizes, int n_in,
                              void* d_out, int out_size)
{
    const float* x    = (const float*)d_in[0];  // (B=1, T, Z, H, W)
    const float* w_ih = (const float*)d_in[1];  // (Z, H, W)
    const float* w_hh = (const float*)d_in[2];
    const float* b_hh = (const float*)d_in[3];
    float* out = (float*)d_out;

    int P = in_sizes[1];            // Z*H*W = 2097152
    int T = in_sizes[0] / P;        // 50 (even)
    int P4 = P / 4;                 // 524288

    int threads = 256;
    int pairs = P4 / 2;             // 262144 threads, 2 float4 each
    int blocks = (pairs + threads - 1) / threads;
    pixelwise_rnn_kernel<<<blocks, threads>>>(
        (const float4*)x, (const float4*)w_ih, (const float4*)w_hh,
        (const float4*)b_hh, (float4*)out, P4, T);
}

// round 10
// speedup vs baseline: 1.0829x; 1.0829x over previous
#include <cuda_runtime.h>

// Pixel-wise diagonal RNN:
//   h_t = leaky_relu(W_ih * x_t + W_hh * h_{t-1} + b_hh), h_0 = 0
// Streaming-bound: 443 MB read + 419 MB write. Strategy (R4 winner):
//  - 2x float4 per thread (32B load granularity, doubled MLP)
//  - __ldcs / __stcs streaming hints (evict-first; no reuse anywhere)
//  - single-timestep loop body; compiler unroll-5 does the load batching
//    within the register budget (explicit 2-step batching regressed: 64-reg
//    cap killed cross-iteration load scheduling — see R6)

#ifndef NEG_SLOPE
#define NEG_SLOPE 0.01f
#endif

__global__ __launch_bounds__(256) void pixelwise_rnn_kernel(
    const float4* __restrict__ x,     // (T, P/4)
    const float4* __restrict__ w_ih,  // (P/4)
    const float4* __restrict__ w_hh,  // (P/4)
    const float4* __restrict__ b_hh,  // (P/4)
    float4* __restrict__ out,         // (T, P/4)
    int P4, int T)
{
    // each thread owns two adjacent float4s: indices 2*tid, 2*tid+1
    int p = 2 * (blockIdx.x * blockDim.x + threadIdx.x);

    const float4 wi0 = w_ih[p],   wi1 = w_ih[p + 1];
    const float4 wh0 = w_hh[p],   wh1 = w_hh[p + 1];
    const float4 b0  = b_hh[p],   b1  = b_hh[p + 1];

    float4 h0 = make_float4(0.f, 0.f, 0.f, 0.f);
    float4 h1 = make_float4(0.f, 0.f, 0.f, 0.f);

    const float4* xp = x + p;
    float4* op = out + p;

    #pragma unroll 5
    for (int t = 0; t < T; ++t) {
        size_t off = (size_t)t * P4;
        float4 xv0 = __ldcs(xp + off);
        float4 xv1 = __ldcs(xp + off + 1);

        float4 v0, v1;
        v0.x = fmaf(wi0.x, xv0.x, fmaf(wh0.x, h0.x, b0.x));
        v0.y = fmaf(wi0.y, xv0.y, fmaf(wh0.y, h0.y, b0.y));
        v0.z = fmaf(wi0.z, xv0.z, fmaf(wh0.z, h0.z, b0.z));
        v0.w = fmaf(wi0.w, xv0.w, fmaf(wh0.w, h0.w, b0.w));
        v1.x = fmaf(wi1.x, xv1.x, fmaf(wh1.x, h1.x, b1.x));
        v1.y = fmaf(wi1.y, xv1.y, fmaf(wh1.y, h1.y, b1.y));
        v1.z = fmaf(wi1.z, xv1.z, fmaf(wh1.z, h1.z, b1.z));
        v1.w = fmaf(wi1.w, xv1.w, fmaf(wh1.w, h1.w, b1.w));

        // leaky_relu with slope in (0,1): max(v, slope*v)
        h0.x = fmaxf(v0.x, NEG_SLOPE * v0.x);
        h0.y = fmaxf(v0.y, NEG_SLOPE * v0.y);
        h0.z = fmaxf(v0.z, NEG_SLOPE * v0.z);
        h0.w = fmaxf(v0.w, NEG_SLOPE * v0.w);
        h1.x = fmaxf(v1.x, NEG_SLOPE * v1.x);
        h1.y = fmaxf(v1.y, NEG_SLOPE * v1.y);
        h1.z = fmaxf(v1.z, NEG_SLOPE * v1.z);
        h1.w = fmaxf(v1.w, NEG_SLOPE * v1.w);

        __stcs(op + off,     h0);
        __stcs(op + off + 1, h1);
    }
}

extern "C" void kernel_launch(void* const* d_in, const int* in_sizes, int n_in,
                              void* d_out, int out_size)
{
    const float* x    = (const float*)d_in[0];  // (B=1, T, Z, H, W)
    const float* w_ih = (const float*)d_in[1];  // (Z, H, W)
    const float* w_hh = (const float*)d_in[2];
    const float* b_hh = (const float*)d_in[3];
    float* out = (float*)d_out;

    int P = in_sizes[1];            // Z*H*W = 2097152
    int T = in_sizes[0] / P;        // 50
    int P4 = P / 4;                 // 524288

    int threads = 256;
    int pairs = P4 / 2;             // 262144 threads, 2 float4 each
    int blocks = (pairs + threads - 1) / threads;
    pixelwise_rnn_kernel<<<blocks, threads>>>(
        (const float4*)x, (const float4*)w_ih, (const float4*)w_hh,
        (const float4*)b_hh, (float4*)out, P4, T);
}